// round 10
// baseline (speedup 1.0000x reference)
#include <cuda_runtime.h>
#include <cuda_bf16.h>
#include <math.h>

#define BSZ   32
#define TLEN  1024
#define DIN   768
#define HD    768
#define G3    2304
#define FCN   512
#define NOUTC 39

typedef unsigned long long ull;
typedef unsigned short u16;

// ---------------------------------------------------------------------------
// Scratch (device globals)
// ---------------------------------------------------------------------------
__device__ float g_xproj [(size_t)BSZ * TLEN * G3];
__device__ float g_xproj2[(size_t)BSZ * TLEN * G3];
__device__ float g_fc    [(size_t)BSZ * TLEN * FCN];
__device__ float g_cb0[G3], g_cb1[G3];
__device__ float g_fcbias[FCN];

__device__ u16 g_fh [(size_t)BSZ * TLEN * DIN], g_fl [(size_t)BSZ * TLEN * DIN];
__device__ u16 g_hhi[(size_t)BSZ * TLEN * HD],  g_hlo[(size_t)BSZ * TLEN * HD];
__device__ u16 g_w0h[(size_t)G3 * DIN], g_w0l[(size_t)G3 * DIN];
__device__ u16 g_w1h[(size_t)G3 * HD],  g_w1l[(size_t)G3 * HD];
__device__ u16 g_fwh[(size_t)FCN * HD], g_fwl[(size_t)FCN * HD];

// Monotonic flags: h-flags +2048/replay, consumer flags +16/replay.
__device__ unsigned g_flags [48 * 32];
__device__ unsigned g_cflags[96 * 32];

// ---------------------------------------------------------------------------
// Helpers
// ---------------------------------------------------------------------------
__device__ __forceinline__ void fma2(ull& d, ull a, ull b) {
    asm("fma.rn.f32x2 %0, %1, %2, %0;" : "+l"(d) : "l"(a), "l"(b));
}
__device__ __forceinline__ ull pack2(float lo, float hi) {
    ull d; asm("mov.b64 %0, {%1, %2};" : "=l"(d) : "f"(lo), "f"(hi)); return d;
}
__device__ __forceinline__ float2 unpack2(ull v) {
    float2 r; asm("mov.b64 {%0, %1}, %2;" : "=f"(r.x), "=f"(r.y) : "l"(v)); return r;
}
__device__ __forceinline__ unsigned bfpk(float hi_src, float lo_src) {
    unsigned r;
    asm("cvt.rn.bf16x2.f32 %0, %1, %2;" : "=r"(r) : "f"(hi_src), "f"(lo_src));
    return r;
}
__device__ __forceinline__ float bflo(unsigned p) { return __uint_as_float(p << 16); }
__device__ __forceinline__ float bfhi(unsigned p) { return __uint_as_float(p & 0xFFFF0000u); }

__device__ __forceinline__ void mma16816(float* d, const unsigned* a, const unsigned* b) {
    asm volatile(
        "mma.sync.aligned.m16n8k16.row.col.f32.bf16.bf16.f32 "
        "{%0,%1,%2,%3}, {%4,%5,%6,%7}, {%8,%9}, {%0,%1,%2,%3};"
        : "+f"(d[0]), "+f"(d[1]), "+f"(d[2]), "+f"(d[3])
        : "r"(a[0]), "r"(a[1]), "r"(a[2]), "r"(a[3]), "r"(b[0]), "r"(b[1]));
}
__device__ __forceinline__ void ldmx4(unsigned* r, unsigned saddr) {
    asm volatile("ldmatrix.sync.aligned.m8n8.x4.shared.b16 {%0,%1,%2,%3}, [%4];"
                 : "=r"(r[0]), "=r"(r[1]), "=r"(r[2]), "=r"(r[3]) : "r"(saddr));
}
__device__ __forceinline__ void ldmx2(unsigned* r, unsigned saddr) {
    asm volatile("ldmatrix.sync.aligned.m8n8.x2.shared.b16 {%0,%1}, [%2];"
                 : "=r"(r[0]), "=r"(r[1]) : "r"(saddr));
}
__device__ __forceinline__ void cp16(void* smem_dst, const void* gsrc) {
    unsigned s = (unsigned)__cvta_generic_to_shared(smem_dst);
    asm volatile("cp.async.cg.shared.global [%0], [%1], 16;" :: "r"(s), "l"(gsrc));
}
__device__ __forceinline__ void cp_commit() { asm volatile("cp.async.commit_group;"); }
template <int N>
__device__ __forceinline__ void cp_wait() {
    asm volatile("cp.async.wait_group %0;" :: "n"(N));
}
__device__ __forceinline__ unsigned ld_acq(const unsigned* p) {
    unsigned v;
    asm volatile("ld.acquire.gpu.global.u32 %0, [%1];" : "=r"(v) : "l"(p) : "memory");
    return v;
}
__device__ __forceinline__ void st_rel(unsigned* p, unsigned v) {
    asm volatile("st.release.gpu.global.u32 [%0], %1;" :: "l"(p), "r"(v) : "memory");
}

// ---------------------------------------------------------------------------
// Prep kernels
// ---------------------------------------------------------------------------
__global__ __launch_bounds__(256) void pack_hl(
    const float* __restrict__ src, u16* __restrict__ dhi, u16* __restrict__ dlo, int n4)
{
    const int i = blockIdx.x * 256 + threadIdx.x;
    if (i >= n4) return;
    float4 v = ((const float4*)src)[i];
    unsigned p0 = bfpk(v.x, v.x), p1 = bfpk(v.y, v.y);
    unsigned p2 = bfpk(v.z, v.z), p3 = bfpk(v.w, v.w);
    float r0 = v.x - bflo(p0), r1 = v.y - bflo(p1);
    float r2 = v.z - bflo(p2), r3 = v.w - bflo(p3);
    unsigned q0 = bfpk(r0, r0), q1 = bfpk(r1, r1);
    unsigned q2 = bfpk(r2, r2), q3 = bfpk(r3, r3);
    ushort4 hi, lo;
    hi.x = (u16)p0; hi.y = (u16)p1; hi.z = (u16)p2; hi.w = (u16)p3;
    lo.x = (u16)q0; lo.y = (u16)q1; lo.z = (u16)q2; lo.w = (u16)q3;
    ((ushort4*)dhi)[i] = hi;
    ((ushort4*)dlo)[i] = lo;
}

__global__ __launch_bounds__(256) void prep_biases(
    const float* __restrict__ bih0, const float* __restrict__ bhh0,
    const float* __restrict__ bih1, const float* __restrict__ bhh1,
    const float* __restrict__ fcb)
{
    const int i = blockIdx.x * 256 + threadIdx.x;
    if (i < G3) {
        g_cb0[i] = bih0[i] + (i < 2 * HD ? bhh0[i] : 0.f);
        g_cb1[i] = bih1[i] + (i < 2 * HD ? bhh1[i] : 0.f);
    }
    if (i < FCN) g_fcbias[i] = fcb[i];
}

// ---------------------------------------------------------------------------
// Split-bf16 GEMM tile (device fn). BM=128, BN=64, BK=64, K=768 fixed.
// Compute gated to warps 0-7; loaders to tid<256. Safe in 512-thread blocks.
// ---------------------------------------------------------------------------
#define GP      144
#define SA_HI   0
#define SA_LO   (128 * GP)
#define SW_HI   (2 * 128 * GP)
#define SW_LO   (SW_HI + 64 * GP)
#define STAGE   (SW_LO + 64 * GP)
#define GSMEM   (2 * STAGE)

__device__ __forceinline__ void gemm_tile_hl(
    char* smg, unsigned sbase,
    const u16* __restrict__ Ah, const u16* __restrict__ Al,
    const u16* __restrict__ Wh, const u16* __restrict__ Wl,
    const float* __restrict__ bias, float* __restrict__ C,
    int m0, int n0, int N, int ACT)
{
    const int tid  = threadIdx.x;
    const int warp = tid >> 5;
    const int lane = tid & 31;
    const int wm   = warp >> 1;
    const int wn   = warp & 1;
    const int lr   = (tid >> 3) & 31;
    const int lc   = tid & 7;
    const bool act25 = (tid < 256);
    const int K = 768, NS = 12;

    float acc[2][4][4];
#pragma unroll
    for (int mt = 0; mt < 2; mt++)
#pragma unroll
        for (int nt = 0; nt < 4; nt++)
#pragma unroll
            for (int e = 0; e < 4; e++) acc[mt][nt][e] = 0.f;

    const int q  = lane >> 3;
    const int rq = (q & 1) * 8 + (lane & 7);
    const int qk = q >> 1;
    const int l2 = lane & 15;
    const int brow = l2 & 7;
    const int bk16 = ((l2 >> 3) & 1) * 16;

    if (act25) {
        char* st = smg;
#pragma unroll
        for (int p = 0; p < 4; p++) {
            const int r = lr + p * 32;
            cp16(st + SA_HI + r * GP + lc * 16, Ah + (size_t)(m0 + r) * K + lc * 8);
            cp16(st + SA_LO + r * GP + lc * 16, Al + (size_t)(m0 + r) * K + lc * 8);
        }
#pragma unroll
        for (int p = 0; p < 2; p++) {
            const int r = lr + p * 32;
            cp16(st + SW_HI + r * GP + lc * 16, Wh + (size_t)(n0 + r) * K + lc * 8);
            cp16(st + SW_LO + r * GP + lc * 16, Wl + (size_t)(n0 + r) * K + lc * 8);
        }
        cp_commit();
    }

    for (int s = 0; s < NS; s++) {
        if (s + 1 < NS) {
            if (act25) {
                const int k0 = (s + 1) * 64;
                char* st = smg + ((s + 1) & 1) * STAGE;
#pragma unroll
                for (int p = 0; p < 4; p++) {
                    const int r = lr + p * 32;
                    cp16(st + SA_HI + r * GP + lc * 16, Ah + (size_t)(m0 + r) * K + k0 + lc * 8);
                    cp16(st + SA_LO + r * GP + lc * 16, Al + (size_t)(m0 + r) * K + k0 + lc * 8);
                }
#pragma unroll
                for (int p = 0; p < 2; p++) {
                    const int r = lr + p * 32;
                    cp16(st + SW_HI + r * GP + lc * 16, Wh + (size_t)(n0 + r) * K + k0 + lc * 8);
                    cp16(st + SW_LO + r * GP + lc * 16, Wl + (size_t)(n0 + r) * K + k0 + lc * 8);
                }
                cp_commit();
            }
            cp_wait<1>();
        } else {
            cp_wait<0>();
        }
        __syncthreads();

        if (warp < 8) {
            const unsigned stA_hi = sbase + (s & 1) * STAGE + SA_HI;
            const unsigned stA_lo = sbase + (s & 1) * STAGE + SA_LO;
            const unsigned stW_hi = sbase + (s & 1) * STAGE + SW_HI;
            const unsigned stW_lo = sbase + (s & 1) * STAGE + SW_LO;
#pragma unroll
            for (int kt = 0; kt < 4; kt++) {
                unsigned ah[2][4], al[2][4], bh2[4][2], bl2[4][2];
#pragma unroll
                for (int mt = 0; mt < 2; mt++) {
                    const int row = wm * 32 + mt * 16 + rq;
                    ldmx4(ah[mt], stA_hi + row * GP + kt * 32 + qk * 16);
                    ldmx4(al[mt], stA_lo + row * GP + kt * 32 + qk * 16);
                }
#pragma unroll
                for (int nt = 0; nt < 4; nt++) {
                    const int row = wn * 32 + nt * 8 + brow;
                    ldmx2(bh2[nt], stW_hi + row * GP + kt * 32 + bk16);
                    ldmx2(bl2[nt], stW_lo + row * GP + kt * 32 + bk16);
                }
#pragma unroll
                for (int mt = 0; mt < 2; mt++)
#pragma unroll
                    for (int nt = 0; nt < 4; nt++) {
                        mma16816(acc[mt][nt], ah[mt], bh2[nt]);
                        mma16816(acc[mt][nt], ah[mt], bl2[nt]);
                        mma16816(acc[mt][nt], al[mt], bh2[nt]);
                    }
            }
        }
        __syncthreads();
    }

    if (warp < 8) {
        const float selu_scale = 1.0507009873554804934193349852946f;
        const float selu_alpha = 1.6732632423543772848170429916717f;
        const int r0 = lane >> 2;
        const int c0 = (lane & 3) * 2;
#pragma unroll
        for (int mt = 0; mt < 2; mt++)
#pragma unroll
            for (int nt = 0; nt < 4; nt++) {
                const int col = n0 + wn * 32 + nt * 8 + c0;
                const float b0 = bias[col], b1 = bias[col + 1];
#pragma unroll
                for (int h = 0; h < 2; h++) {
                    const int row = m0 + wm * 32 + mt * 16 + r0 + h * 8;
                    float v0 = acc[mt][nt][h * 2 + 0] + b0;
                    float v1 = acc[mt][nt][h * 2 + 1] + b1;
                    if (ACT == 1) {
                        v0 = selu_scale * (v0 > 0.f ? v0 : selu_alpha * (expf(v0) - 1.f));
                        v1 = selu_scale * (v1 > 0.f ? v1 : selu_alpha * (expf(v1) - 1.f));
                    }
                    *(float2*)(C + (size_t)row * N + col) = make_float2(v0, v1);
                }
            }
    }
}

// ---------------------------------------------------------------------------
// out_proj (fp32 FFMA2, N=39)
// ---------------------------------------------------------------------------
__global__ __launch_bounds__(256) void gemm_out_tanh(
    const float* __restrict__ A, const float* __restrict__ W,
    const float* __restrict__ bias, float* __restrict__ C,
    int M, int N, int K)
{
    __shared__ float As[8][128];
    __shared__ float Bs[8][128];

    const int tid  = threadIdx.x;
    const int m0   = blockIdx.y * 128;
    const int lrow = tid >> 1;
    const int lk4  = (tid & 1) * 4;
    const int tx = tid & 15;
    const int ty = tid >> 4;

    ull acc2[8][4];
#pragma unroll
    for (int i = 0; i < 8; i++)
#pragma unroll
        for (int j = 0; j < 4; j++) acc2[i][j] = 0ull;

    const float* Arow = A + (size_t)(m0 + lrow) * K + lk4;
    const float* Wrow = W + (size_t)lrow * K + lk4;
    const bool   wok  = lrow < N;

    for (int k0 = 0; k0 < K; k0 += 8) {
        float4 av = *(const float4*)(Arow + k0);
        float4 wv = make_float4(0.f, 0.f, 0.f, 0.f);
        if (wok) wv = *(const float4*)(Wrow + k0);

        __syncthreads();
        As[lk4 + 0][lrow] = av.x; As[lk4 + 1][lrow] = av.y;
        As[lk4 + 2][lrow] = av.z; As[lk4 + 3][lrow] = av.w;
        Bs[lk4 + 0][lrow] = wv.x; Bs[lk4 + 1][lrow] = wv.y;
        Bs[lk4 + 2][lrow] = wv.z; Bs[lk4 + 3][lrow] = wv.w;
        __syncthreads();

#pragma unroll
        for (int kk = 0; kk < 8; kk++) {
            float a[8];
            *(float4*)(a)     = *(const float4*)&As[kk][ty * 4];
            *(float4*)(a + 4) = *(const float4*)&As[kk][64 + ty * 4];
            ulonglong2 b01 = *(const ulonglong2*)&Bs[kk][tx * 4];
            ulonglong2 b23 = *(const ulonglong2*)&Bs[kk][64 + tx * 4];
            ull bb[4] = { b01.x, b01.y, b23.x, b23.y };
            ull aa[8];
#pragma unroll
            for (int i = 0; i < 8; i++) aa[i] = pack2(a[i], a[i]);
#pragma unroll
            for (int i = 0; i < 8; i++)
#pragma unroll
                for (int j = 0; j < 4; j++)
                    fma2(acc2[i][j], aa[i], bb[j]);
        }
    }

#pragma unroll
    for (int i = 0; i < 8; i++) {
        const int m = m0 + ((i < 4) ? (ty * 4 + i) : (64 + ty * 4 + i - 4));
        float* crow = C + (size_t)m * N;
#pragma unroll
        for (int j = 0; j < 4; j++) {
            const int nf = (j < 2) ? (tx * 4 + j * 2) : (64 + tx * 4 + (j - 2) * 2);
            float2 v = unpack2(acc2[i][j]);
            float vals[2] = { v.x, v.y };
#pragma unroll
            for (int s = 0; s < 2; s++) {
                const int n = nf + s;
                if (n < N) crow[n] = tanhf(vals[s] + bias[n]);
            }
        }
    }
}

// ---------------------------------------------------------------------------
// Fused persistent kernel: 48 recurrence blocks + 96 consumer blocks.
// ---------------------------------------------------------------------------
#define NRB      48
#define NCB      96
#define HPB      1552
#define OFF_A_HI 0
#define OFF_A_LO 49664
#define OFF_WLO  99328
#define PSTR     1664
#define RS       52
#define FUS_SMEM 173824

__global__ __launch_bounds__(512, 1) void fused_layer(
    const float* __restrict__ xp,
    const float* __restrict__ w_hh,
    const float* __restrict__ b_hh,
    int mode)
{
    extern __shared__ char smc[];
    unsigned sbase;
    asm("{ .reg .u64 t; cvta.to.shared.u64 t, %1; cvt.u32.u64 %0, t; }"
        : "=r"(sbase) : "l"(smc));
    const int tid = threadIdx.x;

    // ======================= CONSUMER BLOCKS =======================
    if (blockIdx.x >= NRB) {
        const int cid = blockIdx.x - NRB;
        const unsigned cb = ld_acq(&g_cflags[cid * 32]);
        const unsigned hb = (ld_acq(&g_flags[0]) / 2048u) * 2048u
                          + (mode ? 1024u : 0u);

        if (mode == 0) {
            // Phase A: xproj0 chunks (release cflag per chunk)
            for (int tc = 0; tc < 8; tc++) {
                for (int i = cid; i < 1152; i += NCB) {
                    const int b  = i / 36;
                    const int nt = i % 36;
                    gemm_tile_hl(smc, sbase, g_fh, g_fl, g_w0h, g_w0l, g_cb0,
                                 g_xproj, b * TLEN + tc * 128, nt * 64, G3, 0);
                }
                __syncthreads();
                if (tid == 0) st_rel(&g_cflags[cid * 32], cb + (unsigned)(tc + 1));
            }
            // Phase B: xproj1 chunks (trail h flags)
            for (int tc = 0; tc < 8; tc++) {
                const unsigned target = hb + (unsigned)((tc + 1) * 128);
                if (tid < NRB) {
                    while ((int)(ld_acq(&g_flags[tid * 32]) - target) < 0) { }
                }
                __syncthreads();
                for (int i = cid; i < 1152; i += NCB) {
                    const int b  = i / 36;
                    const int nt = i % 36;
                    gemm_tile_hl(smc, sbase, g_hhi, g_hlo, g_w1h, g_w1l, g_cb1,
                                 g_xproj2, b * TLEN + tc * 128, nt * 64, G3, 0);
                }
            }
        } else {
            // fc chunks (trail h flags, release cflag per chunk for cadence)
            for (int tc = 0; tc < 8; tc++) {
                const unsigned target = hb + (unsigned)((tc + 1) * 128);
                if (tid < NRB) {
                    while ((int)(ld_acq(&g_flags[tid * 32]) - target) < 0) { }
                }
                __syncthreads();
                for (int i = cid; i < 256; i += NCB) {
                    const int b  = i / 8;
                    const int nt = i % 8;
                    gemm_tile_hl(smc, sbase, g_hhi, g_hlo, g_fwh, g_fwl, g_fcbias,
                                 g_fc, b * TLEN + tc * 128, nt * 64, FCN, 1);
                }
                __syncthreads();
                if (tid == 0) st_rel(&g_cflags[cid * 32], cb + (unsigned)(tc + 1));
            }
        }
        return;
    }

    // ======================= RECURRENCE BLOCKS =======================
    const int u0g  = blockIdx.x * 16;
    const int warp = tid >> 5;
    const int lane = tid & 31;
    const int ks   = warp & 7;
    const int nh   = warp >> 3;
    const unsigned flag_base = g_flags[blockIdx.x * 32];
    const unsigned cbase     = (flag_base / 2048u) * 16u;
    const bool producer_poll = (mode == 0);

    // W init: hi -> scratch (A region) -> register frags; lo -> permanent smem
    unsigned bh[3][6][2];
    for (int i = tid; i < 48 * 96; i += 512) {
        const int r  = i / 96;
        const int kc = (i % 96) * 8;
        const int gate = r >> 4, ul = r & 15;
        const float* ws = w_hh + (size_t)(gate * HD + u0g + ul) * HD + kc;
        float4 a = *(const float4*)(ws);
        float4 b = *(const float4*)(ws + 4);
        unsigned h0 = bfpk(a.y, a.x), h1 = bfpk(a.w, a.z);
        unsigned h2 = bfpk(b.y, b.x), h3 = bfpk(b.w, b.z);
        unsigned l0 = bfpk(a.y - bfhi(h0), a.x - bflo(h0));
        unsigned l1 = bfpk(a.w - bfhi(h1), a.z - bflo(h1));
        unsigned l2_ = bfpk(b.y - bfhi(h2), b.x - bflo(h2));
        unsigned l3 = bfpk(b.w - bfhi(h3), b.z - bflo(h3));
        *(uint4*)(smc + OFF_A_HI + r * HPB + kc * 2) = make_uint4(h0, h1, h2, h3);
        *(uint4*)(smc + OFF_WLO  + r * HPB + kc * 2) = make_uint4(l0, l1, l2_, l3);
    }
    __syncthreads();
    {
        const int l2 = lane & 15;
#pragma unroll
        for (int nt = 0; nt < 3; nt++)
#pragma unroll
            for (int kt = 0; kt < 6; kt++) {
                const int row = nh * 24 + nt * 8 + (l2 & 7);
                const int kel = ks * 96 + kt * 16 + ((l2 >> 3) & 1) * 8;
                ldmx2(bh[nt][kt], sbase + OFF_A_HI + row * HPB + kel * 2);
            }
    }
    __syncthreads();

    const int bg = tid >> 4;                 // batch 0..31
    const int ug = tid & 15;                 // unit 0..15
    const float bias_n = b_hh[2 * HD + u0g + ug];
    float hprev = 0.f;

    float* prt = (float*)smc;

    const int q   = lane >> 3;
    const int rq  = (q & 1) * 8 + (lane & 7);
    const int l2c = lane & 15;
    const int browc = l2c & 7;
    const int bk8c  = ((l2c >> 3) & 1) * 8;

    // t = 0
    {
        if (producer_poll) {
            if (tid < NCB) {
                while ((int)(ld_acq(&g_cflags[tid * 32]) - (cbase + 1u)) < 0) { }
            }
            __syncthreads();
        }
        const size_t xb = ((size_t)bg * TLEN + 0) * G3 + (u0g + ug);
        const float gi_r = __ldcg(xp + xb);
        const float gi_z = __ldcg(xp + xb + HD);
        const float gi_n = __ldcg(xp + xb + 2 * HD);
        const float r = 1.f / (1.f + expf(-gi_r));
        const float z = 1.f / (1.f + expf(-gi_z));
        const float n = tanhf(gi_n + r * bias_n);
        hprev = (1.f - z) * n;
        const size_t hidx = ((size_t)bg * TLEN + 0) * HD + (u0g + ug);
        unsigned ph = bfpk(hprev, hprev);
        float res = hprev - bflo(ph);
        unsigned pl = bfpk(res, res);
        g_hhi[hidx] = (u16)ph;
        g_hlo[hidx] = (u16)pl;
        __syncthreads();
        if (tid == 0) st_rel(&g_flags[blockIdx.x * 32], flag_base + 1u);
    }

    for (int t = 1; t < TLEN; t++) {
        if (producer_poll && (t & 127) == 0) {
            const unsigned ctar = cbase + (unsigned)((t >> 7) + 1);
            if (tid < NCB) {
                while ((int)(ld_acq(&g_cflags[tid * 32]) - ctar) < 0) { }
            }
            __syncthreads();
        }

        const unsigned need = flag_base + (unsigned)t;
        if (lane < 6) {
            const unsigned* fp = &g_flags[(ks * 6 + lane) * 32];
            while ((int)(ld_acq(fp) - need) < 0) { }
        }
        __syncwarp();

        const size_t xb = ((size_t)bg * TLEN + t) * G3 + (u0g + ug);
        const float gi_r = __ldcg(xp + xb);
        const float gi_z = __ldcg(xp + xb + HD);
        const float gi_n = __ldcg(xp + xb + 2 * HD);

        // stage h_{t-1}: warp (ks,nh) covers rows nh*16..+16, k in its slice
#pragma unroll
        for (int j = 0; j < 12; j++) {
            const int idx = j * 32 + lane;
            const int row = idx / 24;
            const int rem = idx % 24;
            const int pl_ = rem / 12;
            const int kc  = rem % 12;
            const int rowg = nh * 16 + row;
            const size_t gsrc = ((size_t)rowg * TLEN + (t - 1)) * HD + ks * 96 + kc * 8;
            const u16* src = pl_ ? g_hlo : g_hhi;
            uint4 v = __ldcg((const uint4*)(src + gsrc));
            *(uint4*)(smc + (pl_ ? OFF_A_LO : OFF_A_HI)
                      + rowg * HPB + ks * 192 + kc * 16) = v;
        }
        __syncthreads();

        float acc[2][3][4];
#pragma unroll
        for (int mt = 0; mt < 2; mt++)
#pragma unroll
            for (int nt = 0; nt < 3; nt++)
#pragma unroll
                for (int e = 0; e < 4; e++) acc[mt][nt][e] = 0.f;

#pragma unroll
        for (int kt = 0; kt < 6; kt++) {
            const int kel  = ks * 96 + kt * 16 + (q >> 1) * 8;
            const int kelb = ks * 96 + kt * 16 + bk8c;
            unsigned ah[2][4], al[2][4];
#pragma unroll
            for (int mt = 0; mt < 2; mt++) {
                const int row = mt * 16 + rq;
                ldmx4(ah[mt], sbase + OFF_A_HI + row * HPB + kel * 2);
                ldmx4(al[mt], sbase + OFF_A_LO + row * HPB + kel * 2);
            }
#pragma unroll
            for (int nt = 0; nt < 3; nt++) {
                unsigned blf[2];
                ldmx2(blf, sbase + OFF_WLO + (nh * 24 + nt * 8 + browc) * HPB + kelb * 2);
#pragma unroll
                for (int mt = 0; mt < 2; mt++) {
                    mma16816(acc[mt][nt], ah[mt], bh[nt][kt]);
                    mma16816(acc[mt][nt], ah[mt], blf);
                    mma16816(acc[mt][nt], al[mt], bh[nt][kt]);
                }
            }
        }
        __syncthreads();

        {
            const int r0 = lane >> 2;
            const int c0 = (lane & 3) * 2;
            float* wp = prt + ks * PSTR;
#pragma unroll
            for (int mt = 0; mt < 2; mt++)
#pragma unroll
                for (int nt = 0; nt < 3; nt++) {
                    const int rowg = nh * 24 + nt * 8 + c0;
                    const int rb = mt * 16 + r0;
                    *(float2*)(wp + rb * RS + rowg)       = make_float2(acc[mt][nt][0], acc[mt][nt][1]);
                    *(float2*)(wp + (rb + 8) * RS + rowg) = make_float2(acc[mt][nt][2], acc[mt][nt][3]);
                }
        }
        __syncthreads();

        {
            float gh[3];
#pragma unroll
            for (int g = 0; g < 3; g++) {
                const int o = bg * RS + g * 16 + ug;
                float s = 0.f;
#pragma unroll
                for (int k = 0; k < 8; k++) s += prt[k * PSTR + o];
                gh[g] = s;
            }
            const float r = 1.f / (1.f + expf(-(gi_r + gh[0])));
            const float z = 1.f / (1.f + expf(-(gi_z + gh[1])));
            const float n = tanhf(gi_n + r * (gh[2] + bias_n));
            const float hnew = (1.f - z) * n + z * hprev;
            hprev = hnew;
            const size_t hidx = ((size_t)bg * TLEN + t) * HD + (u0g + ug);
            unsigned ph = bfpk(hnew, hnew);
            float res = hnew - bflo(ph);
            unsigned pl = bfpk(res, res);
            g_hhi[hidx] = (u16)ph;
            g_hlo[hidx] = (u16)pl;
        }
        __syncthreads();

        if (tid == 0) st_rel(&g_flags[blockIdx.x * 32], flag_base + (unsigned)(t + 1));
    }
}

// ---------------------------------------------------------------------------
// Launch
// ---------------------------------------------------------------------------
extern "C" void kernel_launch(void* const* d_in, const int* in_sizes, int n_in,
                              void* d_out, int out_size)
{
    const float* features = (const float*)d_in[0];
    const float* w_ih0 = (const float*)d_in[2];
    const float* w_hh0 = (const float*)d_in[3];
    const float* b_ih0 = (const float*)d_in[4];
    const float* b_hh0 = (const float*)d_in[5];
    const float* w_ih1 = (const float*)d_in[6];
    const float* w_hh1 = (const float*)d_in[7];
    const float* b_ih1 = (const float*)d_in[8];
    const float* b_hh1 = (const float*)d_in[9];
    const float* fc_w  = (const float*)d_in[10];
    const float* fc_b  = (const float*)d_in[11];
    const float* out_w = (const float*)d_in[12];
    const float* out_b = (const float*)d_in[13];

    float *xproj, *xproj2, *fcb;
    u16 *fh, *fl, *w0h, *w0l, *w1h, *w1l, *fwh, *fwl;
    cudaGetSymbolAddress((void**)&xproj,  g_xproj);
    cudaGetSymbolAddress((void**)&xproj2, g_xproj2);
    cudaGetSymbolAddress((void**)&fcb,    g_fc);
    cudaGetSymbolAddress((void**)&fh,  g_fh);
    cudaGetSymbolAddress((void**)&fl,  g_fl);
    cudaGetSymbolAddress((void**)&w0h, g_w0h);
    cudaGetSymbolAddress((void**)&w0l, g_w0l);
    cudaGetSymbolAddress((void**)&w1h, g_w1h);
    cudaGetSymbolAddress((void**)&w1l, g_w1l);
    cudaGetSymbolAddress((void**)&fwh, g_fwh);
    cudaGetSymbolAddress((void**)&fwl, g_fwl);

    static bool attr_set = false;
    if (!attr_set) {
        cudaFuncSetAttribute(fused_layer,
                             cudaFuncAttributeMaxDynamicSharedMemorySize, (int)FUS_SMEM);
        attr_set = true;
    }

    const int M = BSZ * TLEN;

    // Prep
    {
        int n4 = (BSZ * TLEN * DIN) / 4;
        pack_hl<<<(n4 + 255) / 256, 256>>>(features, fh, fl, n4);
        n4 = (G3 * DIN) / 4;
        pack_hl<<<(n4 + 255) / 256, 256>>>(w_ih0, w0h, w0l, n4);
        n4 = (G3 * HD) / 4;
        pack_hl<<<(n4 + 255) / 256, 256>>>(w_ih1, w1h, w1l, n4);
        n4 = (FCN * HD) / 4;
        pack_hl<<<(n4 + 255) / 256, 256>>>(fc_w, fwh, fwl, n4);
        prep_biases<<<(G3 + 255) / 256, 256>>>(b_ih0, b_hh0, b_ih1, b_hh1, fc_b);
    }

    // Launch 1: layer-0 recurrence + consumers (xproj0 chunks, then xproj1)
    fused_layer<<<NRB + NCB, 512, FUS_SMEM>>>(xproj, w_hh0, b_hh0, 0);

    // Launch 2: layer-1 recurrence + consumers (fc chunks)
    fused_layer<<<NRB + NCB, 512, FUS_SMEM>>>(xproj2, w_hh1, b_hh1, 1);

    // out_proj + tanh
    gemm_out_tanh<<<dim3(1, M / 128), 256>>>(fcb, out_w, out_b, (float*)d_out,
                                             M, NOUTC, FCN);
}